// round 2
// baseline (speedup 1.0000x reference)
#include <cuda_runtime.h>
#include <cstdint>

#define NN      16384      // N_NODES
#define NP      8192       // N_PARENTS
#define NL      8192       // leaves
#define KW      32
#define H       64
#define VOCAB   100000
#define NCLASS  4

#define WPITCH  65         // smem pitch for scalar-read weight tiles (conflict-free)
#define UPITCH  66         // smem pitch for float2-read U tiles (even, conflict-free)

// ---------------- device scratch (no allocations allowed) ----------------
__device__ float g_ET[(size_t)VOCAB * H];     // 25.6 MB  E transposed (VOCAB, H)
__device__ float g_xe[(size_t)NN * H];        // 4 MB     xe
__device__ float g_h [(size_t)NN * H];        // 4 MB     node_h
__device__ float g_A [(size_t)NP * 4 * H];    // 8 MB     Az,Ar,Ah,q per parent
__device__ int   g_flag[NP];                  // ready flags for parents
__device__ float g_partial[64 * H];           // max-reduction partials

__device__ __forceinline__ float sigm(float x) { return 1.f / (1.f + __expf(-x)); }

// ---------------- kernel 0: reset flags ----------------
__global__ void k_init() {
    int i = blockIdx.x * blockDim.x + threadIdx.x;
    if (i < NP) g_flag[i] = 0;
}

// ---------------- kernel 1: transpose E (H, VOCAB) -> (VOCAB, H) ----------------
// VOCAB = 100000 = 3125 * 32 exactly.
__global__ void k_transpose(const float* __restrict__ E) {
    __shared__ float sm[64][33];
    int v0 = blockIdx.x * 32;
    int tid = threadIdx.x;
    int vv = tid & 31, hh = tid >> 5;          // 8 rows per pass
#pragma unroll
    for (int h0 = 0; h0 < 64; h0 += 8)
        sm[h0 + hh][vv] = E[(size_t)(h0 + hh) * VOCAB + v0 + vv];
    __syncthreads();
#pragma unroll
    for (int i = tid; i < 2048; i += 256) {
        int v = i >> 6, h = i & 63;
        g_ET[(size_t)(v0 + v) * H + h] = sm[h][v];
    }
}

// ---------------- kernel 2: xe[n,h] = sum_k x_word[n,k] * E_T[idx[n,k], h] ----------------
// one warp per node; lane owns h = 2*lane, 2*lane+1
__global__ void __launch_bounds__(256) k_embed(const float* __restrict__ xw,
                                               const int* __restrict__ xi) {
    int warp = (blockIdx.x * blockDim.x + threadIdx.x) >> 5;
    int lane = threadIdx.x & 31;
    if (warp >= NN) return;
    float w  = xw[warp * KW + lane];
    int   ix = xi[warp * KW + lane];
    float2 acc = make_float2(0.f, 0.f);
#pragma unroll 4
    for (int j = 0; j < 32; j++) {
        int   idx = __shfl_sync(0xffffffffu, ix, j);
        float wj  = __shfl_sync(0xffffffffu, w,  j);
        float2 e = *(const float2*)(&g_ET[(size_t)idx * H + 2 * lane]);
        acc.x += wj * e.x;
        acc.y += wj * e.y;
    }
    *(float2*)(&g_xe[(size_t)warp * H + 2 * lane]) = acc;
}

// ---------------- kernel 3: leaf h + parent precompute ----------------
// block = 256 threads, 16 nodes/block (thread = (h2, group), 4 nodes per thread).
// L = 8192 is a multiple of 16 -> each block is all-leaf or all-parent.
__global__ void k_precompute(const float* __restrict__ Wz, const float* __restrict__ Wr,
                             const float* __restrict__ Wh, const float* __restrict__ Wa,
                             const float* __restrict__ bz, const float* __restrict__ br,
                             const float* __restrict__ bh) {
    extern __shared__ float sm[];
    float* sW = sm;                         // 4 * 64 * WPITCH  (input-major, padded)
    float* sb = sW + 4 * 64 * WPITCH;       // 3 * 64
    float* sx = sb + 3 * 64;                // 16 * 64
    int tid = threadIdx.x;

    const float* Ws[4] = {Wz, Wr, Wh, Wa};
    for (int m = 0; m < 4; m++) {
        const float* W = Ws[m];
        for (int i = tid; i < 4096; i += 256) {
            int h2 = i >> 6, h = i & 63;     // coalesced global read W[i] = W[h2][h]
            float v = W[i];
            if (m < 3) sW[m * 64 * WPITCH + h  * WPITCH + h2] = v;  // coeff(in=h, out=h2)
            else       sW[m * 64 * WPITCH + h2 * WPITCH + h ] = v;  // attn: q = xe @ Wa (in=h2,out=h)
        }
    }
    if (tid < 64) { sb[tid] = bz[tid]; sb[64 + tid] = br[tid]; sb[128 + tid] = bh[tid]; }

    int base = blockIdx.x * 16;
    for (int i = tid; i < 16 * 64; i += 256)
        sx[i] = g_xe[(size_t)base * H + i];
    __syncthreads();

    int h2 = tid & 63, grp = tid >> 6;
    const float* x0 = sx + grp * 4 * 64;
    float az[4] = {0, 0, 0, 0}, ar[4] = {0, 0, 0, 0};
    float ah[4] = {0, 0, 0, 0}, aq[4] = {0, 0, 0, 0};
#pragma unroll 4
    for (int h = 0; h < 64; h++) {
        float wz = sW[0 * 64 * WPITCH + h * WPITCH + h2];
        float wr = sW[1 * 64 * WPITCH + h * WPITCH + h2];
        float wh = sW[2 * 64 * WPITCH + h * WPITCH + h2];
        float wa = sW[3 * 64 * WPITCH + h * WPITCH + h2];
#pragma unroll
        for (int nb = 0; nb < 4; nb++) {
            float x = x0[nb * 64 + h];
            az[nb] += x * wz; ar[nb] += x * wr;
            ah[nb] += x * wh; aq[nb] += x * wa;
        }
    }

    if (base < NL) {
#pragma unroll
        for (int nb = 0; nb < 4; nb++) {
            int gn = base + grp * 4 + nb;
            float z = sigm(az[nb] + sb[h2]);
            float c = tanhf(ah[nb] + sb[128 + h2]);
            g_h[(size_t)gn * H + h2] = (1.f - z) * c;
        }
    } else {
#pragma unroll
        for (int nb = 0; nb < 4; nb++) {
            int p = base - NL + grp * 4 + nb;
            float* Ap = g_A + (size_t)p * 256;
            Ap[h2]        = az[nb] + sb[h2];        // Az + bz
            Ap[64  + h2]  = ar[nb] + sb[64 + h2];   // Ar + br
            Ap[128 + h2]  = ah[nb] + sb[128 + h2];  // Ah + bh
            Ap[192 + h2]  = aq[nb];                 // q (no bias)
        }
    }
}

// ---------------- kernel 4: persistent dependency-ordered parent GRU ----------------
// one warp per parent slot; warp w handles parents w, w+W, ... (all deps point backwards,
// grid sized so ALL blocks are co-resident -> spin-waits are deadlock-free).
__global__ void __launch_bounds__(256) k_parents(const float* __restrict__ Uz,
                                                 const float* __restrict__ Ur,
                                                 const float* __restrict__ Uh,
                                                 const int*   __restrict__ tree) {
    extern __shared__ float sm[];
    float* sU = sm;                          // 3 * 64 * UPITCH, input-major (U^T), padded
    float* sv = sU + 3 * 64 * UPITCH;        // 8 warps * 64 (h_tilde / r*h_tilde buffer)
    int tid = threadIdx.x;

    const float* Us[3] = {Uz, Ur, Uh};
    for (int m = 0; m < 3; m++) {
        const float* U = Us[m];
        for (int i = tid; i < 4096; i += 256) {
            int h2 = i >> 6, h = i & 63;      // coalesced read U[h2][h]
            sU[m * 64 * UPITCH + h * UPITCH + h2] = U[i];
        }
    }
    __syncthreads();

    int wid = tid >> 5, lane = tid & 31;
    int gwarp = blockIdx.x * 8 + wid;
    int nwarp = gridDim.x * 8;
    float* svw = sv + wid * 64;
    const float* sUz = sU;
    const float* sUr = sU + 64 * UPITCH;
    const float* sUh = sU + 2 * 64 * UPITCH;

    for (int p = gwarp; p < NP; p += nwarp) {
        const int* tr = tree + (size_t)p * 5;
        int c0 = __ldg(tr + 0), c1 = __ldg(tr + 1), c2 = __ldg(tr + 2), c3 = __ldg(tr + 3);

        // spin-wait on parent children (lanes 0..3, one child each)
        if (lane < 4) {
            int c = (lane == 0) ? c0 : (lane == 1) ? c1 : (lane == 2) ? c2 : c3;
            if (c >= NL) {
                volatile int* f = &g_flag[c - NL];
                while (*f == 0) { __nanosleep(40); }
            }
        }
        __syncwarp();
        __threadfence();   // acquire: order child loads after flag observation

        float2 ch0, ch1, ch2, ch3;
        ch0 = (c0 >= 0) ? __ldcg((const float2*)(g_h + (size_t)c0 * H) + lane) : make_float2(0.f, 0.f);
        ch1 = (c1 >= 0) ? __ldcg((const float2*)(g_h + (size_t)c1 * H) + lane) : make_float2(0.f, 0.f);
        ch2 = (c2 >= 0) ? __ldcg((const float2*)(g_h + (size_t)c2 * H) + lane) : make_float2(0.f, 0.f);
        ch3 = (c3 >= 0) ? __ldcg((const float2*)(g_h + (size_t)c3 * H) + lane) : make_float2(0.f, 0.f);

        const float* Ap = g_A + (size_t)p * 256;
        float2 qv = ((const float2*)(Ap + 192))[lane];

        // attention logits: l_j = sigmoid(q . child_j), warp reduction
        float p0 = qv.x * ch0.x + qv.y * ch0.y;
        float p1 = qv.x * ch1.x + qv.y * ch1.y;
        float p2 = qv.x * ch2.x + qv.y * ch2.y;
        float p3 = qv.x * ch3.x + qv.y * ch3.y;
#pragma unroll
        for (int o = 16; o > 0; o >>= 1) {
            p0 += __shfl_xor_sync(0xffffffffu, p0, o);
            p1 += __shfl_xor_sync(0xffffffffu, p1, o);
            p2 += __shfl_xor_sync(0xffffffffu, p2, o);
            p3 += __shfl_xor_sync(0xffffffffu, p3, o);
        }
        float l0 = (c0 >= 0) ? sigm(p0) : -1e30f;
        float l1 = (c1 >= 0) ? sigm(p1) : -1e30f;
        float l2 = (c2 >= 0) ? sigm(p2) : -1e30f;
        float l3 = (c3 >= 0) ? sigm(p3) : -1e30f;
        float mx = fmaxf(fmaxf(l0, l1), fmaxf(l2, l3));
        float a0 = (c0 >= 0) ? __expf(l0 - mx) : 0.f;
        float a1 = (c1 >= 0) ? __expf(l1 - mx) : 0.f;
        float a2 = (c2 >= 0) ? __expf(l2 - mx) : 0.f;
        float a3 = (c3 >= 0) ? __expf(l3 - mx) : 0.f;
        float inv = 1.f / (a0 + a1 + a2 + a3);
        a0 *= inv; a1 *= inv; a2 *= inv; a3 *= inv;

        float2 ht;
        ht.x = a0 * ch0.x + a1 * ch1.x + a2 * ch2.x + a3 * ch3.x;
        ht.y = a0 * ch0.y + a1 * ch1.y + a2 * ch2.y + a3 * ch3.y;

        ((float2*)svw)[lane] = ht;
        __syncwarp();

        float2 accz = make_float2(0.f, 0.f), accr = make_float2(0.f, 0.f);
#pragma unroll 4
        for (int h = 0; h < 64; h++) {
            float  b  = svw[h];
            float2 uz = *(const float2*)(sUz + h * UPITCH + 2 * lane);
            float2 ur = *(const float2*)(sUr + h * UPITCH + 2 * lane);
            accz.x += b * uz.x; accz.y += b * uz.y;
            accr.x += b * ur.x; accr.y += b * ur.y;
        }
        float2 Az = ((const float2*)(Ap      ))[lane];
        float2 Ar = ((const float2*)(Ap + 64 ))[lane];
        float2 Ah = ((const float2*)(Ap + 128))[lane];
        float2 z = make_float2(sigm(Az.x + accz.x), sigm(Az.y + accz.y));
        float2 r = make_float2(sigm(Ar.x + accr.x), sigm(Ar.y + accr.y));

        __syncwarp();
        ((float2*)svw)[lane] = make_float2(r.x * ht.x, r.y * ht.y);
        __syncwarp();

        float2 accc = make_float2(0.f, 0.f);
#pragma unroll 4
        for (int h = 0; h < 64; h++) {
            float  b  = svw[h];
            float2 uh = *(const float2*)(sUh + h * UPITCH + 2 * lane);
            accc.x += b * uh.x; accc.y += b * uh.y;
        }
        float2 cv = make_float2(tanhf(Ah.x + accc.x), tanhf(Ah.y + accc.y));
        float2 hv;
        hv.x = z.x * ht.x + (1.f - z.x) * cv.x;
        hv.y = z.y * ht.y + (1.f - z.y) * cv.y;
        ((float2*)(g_h + (size_t)(NL + p) * H))[lane] = hv;

        __threadfence();   // release: data visible before flag
        __syncwarp();
        if (lane == 0) *(volatile int*)&g_flag[p] = 1;
    }
}

// ---------------- kernel 5: per-column max over parents (partial) ----------------
__global__ void k_rmax() {
    __shared__ float sred[4][64];
    int tid = threadIdx.x;               // 256
    int h2 = tid & 63, g = tid >> 6;
    int p0 = blockIdx.x * 128;
    float m = -1e30f;
    for (int r = g; r < 128; r += 4)
        m = fmaxf(m, g_h[(size_t)(NL + p0 + r) * H + h2]);
    sred[g][h2] = m;
    __syncthreads();
    if (tid < 64) {
        float mm = fmaxf(fmaxf(sred[0][tid], sred[1][tid]),
                         fmaxf(sred[2][tid], sred[3][tid]));
        g_partial[blockIdx.x * 64 + tid] = mm;
    }
}

// ---------------- kernel 6: final max + logits + softmax ----------------
__global__ void k_final(const float* __restrict__ Wout, const float* __restrict__ bout,
                        float* __restrict__ out) {
    __shared__ float fm[64];
    __shared__ float lg[4];
    int tid = threadIdx.x;               // 64
    float m = -1e30f;
    for (int b = 0; b < 64; b++) m = fmaxf(m, g_partial[b * 64 + tid]);
    fm[tid] = m;
    __syncthreads();
    if (tid < NCLASS) {
        float s = bout[tid];
        for (int h = 0; h < 64; h++) s += Wout[tid * 64 + h] * fm[h];
        lg[tid] = s;
    }
    __syncthreads();
    if (tid == 0) {
        float mx = fmaxf(fmaxf(lg[0], lg[1]), fmaxf(lg[2], lg[3]));
        float e0 = __expf(lg[0] - mx), e1 = __expf(lg[1] - mx);
        float e2 = __expf(lg[2] - mx), e3 = __expf(lg[3] - mx);
        float s = e0 + e1 + e2 + e3;
        out[0] = e0 / s; out[1] = e1 / s; out[2] = e2 / s; out[3] = e3 / s;
    }
}

// ---------------- launch ----------------
extern "C" void kernel_launch(void* const* d_in, const int* in_sizes, int n_in,
                              void* d_out, int out_size) {
    const float* x_word  = (const float*)d_in[0];
    const int*   x_index = (const int*)  d_in[1];
    const int*   tree    = (const int*)  d_in[2];
    const float* E       = (const float*)d_in[3];
    const float* Wz      = (const float*)d_in[4];
    const float* Uz      = (const float*)d_in[5];
    const float* bz      = (const float*)d_in[6];
    const float* Wr      = (const float*)d_in[7];
    const float* Ur      = (const float*)d_in[8];
    const float* br      = (const float*)d_in[9];
    const float* Wh      = (const float*)d_in[10];
    const float* Uh      = (const float*)d_in[11];
    const float* bh      = (const float*)d_in[12];
    const float* Wa      = (const float*)d_in[13];
    const float* Wout    = (const float*)d_in[14];
    const float* bout    = (const float*)d_in[15];
    float* out = (float*)d_out;

    const int smemPre = (4 * 64 * WPITCH + 3 * 64 + 16 * 64) * 4;   // 71424 B
    const int smemPar = (3 * 64 * UPITCH + 8 * 64) * 4;             // 52736 B
    cudaFuncSetAttribute(k_precompute, cudaFuncAttributeMaxDynamicSharedMemorySize, smemPre);
    cudaFuncSetAttribute(k_parents,    cudaFuncAttributeMaxDynamicSharedMemorySize, smemPar);

    int dev = 0;
    cudaGetDevice(&dev);
    int sms = 0;
    if (cudaDeviceGetAttribute(&sms, cudaDevAttrMultiProcessorCount, dev) != cudaSuccess || sms <= 0)
        sms = 148;
    int nb = 0;
    if (cudaOccupancyMaxActiveBlocksPerMultiprocessor(&nb, k_parents, 256, smemPar) != cudaSuccess || nb < 1)
        nb = 1;
    int pgrid = sms * nb;                  // guaranteed co-resident
    if (pgrid > NP / 8) pgrid = NP / 8;    // no more warps than parents needed
    if (pgrid < 1) pgrid = 1;

    k_init<<<32, 256>>>();
    k_transpose<<<3125, 256>>>(E);
    k_embed<<<2048, 256>>>(x_word, x_index);
    k_precompute<<<1024, 256, smemPre>>>(Wz, Wr, Wh, Wa, bz, br, bh);
    k_parents<<<pgrid, 256, smemPar>>>(Uz, Ur, Uh, tree);
    k_rmax<<<64, 256>>>();
    k_final<<<1, 64>>>(Wout, bout, out);
}

// round 5
// speedup vs baseline: 1.0381x; 1.0381x over previous
#include <cuda_runtime.h>
#include <cstdint>

#define NN      16384      // N_NODES
#define NP      8192       // N_PARENTS
#define NL      8192       // leaves
#define KW      32
#define H       64
#define VOCAB   100000
#define NCLASS  4

#define WPITCH  65         // smem pitch for scalar-read weight tiles (conflict-free)
#define UPITCH  66         // smem pitch for float2-read U tiles (even, conflict-free)

// ---------------- device scratch (no allocations allowed) ----------------
__device__ __align__(16) float g_ET[(size_t)VOCAB * H];   // 25.6 MB  E transposed
__device__ __align__(16) float g_xe[(size_t)NN * H];      // 4 MB     xe
__device__ __align__(16) float g_h [(size_t)NN * H];      // 4 MB     node_h
__device__ __align__(16) float g_WT[4 * H * H];           // 64 KB    Wz^T,Wr^T,Wh^T,Wa (in,out)
__device__ int   g_flag[NP];                              // ready flags for parents
__device__ float g_partial[64 * H];                       // max-reduction partials

__device__ __forceinline__ float sigm(float x) { return 1.f / (1.f + __expf(-x)); }

// ---------------- kernel 0: reset flags + build WT ----------------
// Wz/Wr/Wh: stored transposed WT[h][h2] = W[h2][h]  (computes xe @ W^T)
// Wa:       stored DIRECT     WT[h][h2] = Wa[h][h2] (computes xe @ Wa — reference has no .T here!)
__global__ void k_prep(const float* __restrict__ Wz, const float* __restrict__ Wr,
                       const float* __restrict__ Wh, const float* __restrict__ Wa) {
    if (blockIdx.x < 3) {
        __shared__ float t[64][65];
        const float* W = (blockIdx.x == 0) ? Wz : (blockIdx.x == 1) ? Wr : Wh;
        int tid = threadIdx.x;
        for (int i = tid; i < 4096; i += 256) {
            int r = i >> 6, c = i & 63;        // coalesced read W[r][c]
            t[r][c] = W[i];
        }
        __syncthreads();
        float* WT = g_WT + blockIdx.x * 4096;
        for (int i = tid; i < 4096; i += 256) {
            int h = i >> 6, h2 = i & 63;       // coalesced write WT[h][h2] = W[h2][h]
            WT[i] = t[h2][h];
        }
    } else if (blockIdx.x == 3) {
        // Wa: straight copy (q = xe @ Wa)
        int tid = threadIdx.x;
        float* WT = g_WT + 3 * 4096;
        for (int i = tid; i < 4096; i += 256)
            WT[i] = Wa[i];
    } else {
        int i = (blockIdx.x - 4) * 256 + threadIdx.x;
        if (i < NP) g_flag[i] = 0;
    }
}

// ---------------- kernel 1: transpose E (H, VOCAB) -> (VOCAB, H) ----------------
__global__ void k_transpose(const float* __restrict__ E) {
    __shared__ float sm[64][33];
    int v0 = blockIdx.x * 32;
    int tid = threadIdx.x;
    int vv = tid & 31, hh = tid >> 5;
#pragma unroll
    for (int h0 = 0; h0 < 64; h0 += 8)
        sm[h0 + hh][vv] = E[(size_t)(h0 + hh) * VOCAB + v0 + vv];
    __syncthreads();
#pragma unroll
    for (int i = tid; i < 2048; i += 256) {
        int v = i >> 6, h = i & 63;
        g_ET[(size_t)(v0 + v) * H + h] = sm[h][v];
    }
}

// ---------------- kernel 2: xe[n,h] = sum_k x_word[n,k] * E_T[idx[n,k], h] ----------------
__global__ void __launch_bounds__(256) k_embed(const float* __restrict__ xw,
                                               const int* __restrict__ xi) {
    int warp = (blockIdx.x * blockDim.x + threadIdx.x) >> 5;
    int lane = threadIdx.x & 31;
    if (warp >= NN) return;
    float w  = xw[warp * KW + lane];
    int   ix = xi[warp * KW + lane];
    float2 acc = make_float2(0.f, 0.f);
#pragma unroll 4
    for (int j = 0; j < 32; j++) {
        int   idx = __shfl_sync(0xffffffffu, ix, j);
        float wj  = __shfl_sync(0xffffffffu, w,  j);
        float2 e = *(const float2*)(&g_ET[(size_t)idx * H + 2 * lane]);
        acc.x += wj * e.x;
        acc.y += wj * e.y;
    }
    *(float2*)(&g_xe[(size_t)warp * H + 2 * lane]) = acc;
}

// ---------------- kernel 3: leaf h only (z,c gates; 2 matrices) ----------------
__global__ void k_leaf(const float* __restrict__ Wz, const float* __restrict__ Wh,
                       const float* __restrict__ bz, const float* __restrict__ bh) {
    extern __shared__ float sm[];
    float* sW = sm;                         // 2 * 64 * WPITCH (input-major)
    float* sb = sW + 2 * 64 * WPITCH;       // 2 * 64
    float* sx = sb + 2 * 64;                // 16 * 64
    int tid = threadIdx.x;

    for (int m = 0; m < 2; m++) {
        const float* W = m ? Wh : Wz;
        for (int i = tid; i < 4096; i += 256) {
            int h2 = i >> 6, h = i & 63;
            sW[m * 64 * WPITCH + h * WPITCH + h2] = W[i];
        }
    }
    if (tid < 64) { sb[tid] = bz[tid]; sb[64 + tid] = bh[tid]; }

    int base = blockIdx.x * 16;
    for (int i = tid; i < 16 * 64; i += 256)
        sx[i] = g_xe[(size_t)base * H + i];
    __syncthreads();

    int h2 = tid & 63, grp = tid >> 6;
    const float* x0 = sx + grp * 4 * 64;
    float az[4] = {0, 0, 0, 0}, ah[4] = {0, 0, 0, 0};
#pragma unroll 8
    for (int h = 0; h < 64; h++) {
        float wz = sW[h * WPITCH + h2];
        float wh = sW[64 * WPITCH + h * WPITCH + h2];
#pragma unroll
        for (int nb = 0; nb < 4; nb++) {
            float x = x0[nb * 64 + h];
            az[nb] += x * wz; ah[nb] += x * wh;
        }
    }
#pragma unroll
    for (int nb = 0; nb < 4; nb++) {
        int gn = base + grp * 4 + nb;
        float z = sigm(az[nb] + sb[h2]);
        float c = tanhf(ah[nb] + sb[64 + h2]);
        g_h[(size_t)gn * H + h2] = (1.f - z) * c;
    }
}

// ---------------- kernel 4: persistent dependency-ordered parent GRU ----------------
__global__ void __launch_bounds__(256, 4) k_parents(const float* __restrict__ Uz,
                                                    const float* __restrict__ Ur,
                                                    const float* __restrict__ Uh,
                                                    const int*   __restrict__ tree,
                                                    const float* __restrict__ bz,
                                                    const float* __restrict__ br,
                                                    const float* __restrict__ bh) {
    extern __shared__ float sm[];
    float* sU = sm;                          // 3 * 64 * UPITCH, input-major (U^T)
    float* sv = sU + 3 * 64 * UPITCH;        // 8 warps * 64
    int tid = threadIdx.x;

    const float* Us[3] = {Uz, Ur, Uh};
    for (int m = 0; m < 3; m++) {
        const float* U = Us[m];
        for (int i = tid; i < 4096; i += 256) {
            int h2 = i >> 6, h = i & 63;
            sU[m * 64 * UPITCH + h * UPITCH + h2] = U[i];
        }
    }
    __syncthreads();

    int wid = tid >> 5, lane = tid & 31;
    int gwarp = blockIdx.x * 8 + wid;
    int nwarp = gridDim.x * 8;
    float* svw = sv + wid * 64;
    const float* sUz = sU;
    const float* sUr = sU + 64 * UPITCH;
    const float* sUh = sU + 2 * 64 * UPITCH;

    float2 bz2 = __ldg((const float2*)bz + lane);
    float2 br2 = __ldg((const float2*)br + lane);
    float2 bh2 = __ldg((const float2*)bh + lane);

    for (int p = gwarp; p < NP; p += nwarp) {
        const int* tr = tree + (size_t)p * 5;
        int c0 = __ldg(tr + 0), c1 = __ldg(tr + 1), c2 = __ldg(tr + 2), c3 = __ldg(tr + 3);

        // ---- fused A precompute: az/ar/ah = xe@W^T + b ; aq = xe@Wa ----
        float2 xe2 = __ldcg((const float2*)(g_xe + (size_t)(NL + p) * H) + lane);
        float2 az = bz2, ar = br2, ah = bh2, aq = make_float2(0.f, 0.f);
#pragma unroll 8
        for (int h = 0; h < 64; h++) {
            float b = __shfl_sync(0xffffffffu, (h & 1) ? xe2.y : xe2.x, h >> 1);
            float2 wz = __ldg((const float2*)(g_WT            + h * 64) + lane);
            float2 wr = __ldg((const float2*)(g_WT + 1 * 4096 + h * 64) + lane);
            float2 wh = __ldg((const float2*)(g_WT + 2 * 4096 + h * 64) + lane);
            float2 wa = __ldg((const float2*)(g_WT + 3 * 4096 + h * 64) + lane);
            az.x += b * wz.x; az.y += b * wz.y;
            ar.x += b * wr.x; ar.y += b * wr.y;
            ah.x += b * wh.x; ah.y += b * wh.y;
            aq.x += b * wa.x; aq.y += b * wa.y;
        }

        // ---- spin-wait on parent children (lanes 0..3) ----
        if (lane < 4) {
            int c = (lane == 0) ? c0 : (lane == 1) ? c1 : (lane == 2) ? c2 : c3;
            if (c >= NL) {
                volatile int* f = &g_flag[c - NL];
                while (*f == 0) { __nanosleep(20); }
            }
        }
        __syncwarp();
        __threadfence();   // acquire

        float2 ch0, ch1, ch2, ch3;
        ch0 = (c0 >= 0) ? __ldcg((const float2*)(g_h + (size_t)c0 * H) + lane) : make_float2(0.f, 0.f);
        ch1 = (c1 >= 0) ? __ldcg((const float2*)(g_h + (size_t)c1 * H) + lane) : make_float2(0.f, 0.f);
        ch2 = (c2 >= 0) ? __ldcg((const float2*)(g_h + (size_t)c2 * H) + lane) : make_float2(0.f, 0.f);
        ch3 = (c3 >= 0) ? __ldcg((const float2*)(g_h + (size_t)c3 * H) + lane) : make_float2(0.f, 0.f);

        // attention logits l_j = sigmoid(q . child_j)
        float p0 = aq.x * ch0.x + aq.y * ch0.y;
        float p1 = aq.x * ch1.x + aq.y * ch1.y;
        float p2 = aq.x * ch2.x + aq.y * ch2.y;
        float p3 = aq.x * ch3.x + aq.y * ch3.y;
#pragma unroll
        for (int o = 16; o > 0; o >>= 1) {
            p0 += __shfl_xor_sync(0xffffffffu, p0, o);
            p1 += __shfl_xor_sync(0xffffffffu, p1, o);
            p2 += __shfl_xor_sync(0xffffffffu, p2, o);
            p3 += __shfl_xor_sync(0xffffffffu, p3, o);
        }
        float l0 = (c0 >= 0) ? sigm(p0) : -1e30f;
        float l1 = (c1 >= 0) ? sigm(p1) : -1e30f;
        float l2 = (c2 >= 0) ? sigm(p2) : -1e30f;
        float l3 = (c3 >= 0) ? sigm(p3) : -1e30f;
        float mx = fmaxf(fmaxf(l0, l1), fmaxf(l2, l3));
        float a0 = (c0 >= 0) ? __expf(l0 - mx) : 0.f;
        float a1 = (c1 >= 0) ? __expf(l1 - mx) : 0.f;
        float a2 = (c2 >= 0) ? __expf(l2 - mx) : 0.f;
        float a3 = (c3 >= 0) ? __expf(l3 - mx) : 0.f;
        float inv = 1.f / (a0 + a1 + a2 + a3);
        a0 *= inv; a1 *= inv; a2 *= inv; a3 *= inv;

        float2 ht;
        ht.x = a0 * ch0.x + a1 * ch1.x + a2 * ch2.x + a3 * ch3.x;
        ht.y = a0 * ch0.y + a1 * ch1.y + a2 * ch2.y + a3 * ch3.y;

        ((float2*)svw)[lane] = ht;
        __syncwarp();

        float2 accz = make_float2(0.f, 0.f), accr = make_float2(0.f, 0.f);
#pragma unroll 4
        for (int h = 0; h < 64; h++) {
            float  b  = svw[h];
            float2 uz = *(const float2*)(sUz + h * UPITCH + 2 * lane);
            float2 ur = *(const float2*)(sUr + h * UPITCH + 2 * lane);
            accz.x += b * uz.x; accz.y += b * uz.y;
            accr.x += b * ur.x; accr.y += b * ur.y;
        }
        float2 z = make_float2(sigm(az.x + accz.x), sigm(az.y + accz.y));
        float2 r = make_float2(sigm(ar.x + accr.x), sigm(ar.y + accr.y));

        __syncwarp();
        ((float2*)svw)[lane] = make_float2(r.x * ht.x, r.y * ht.y);
        __syncwarp();

        float2 accc = make_float2(0.f, 0.f);
#pragma unroll 4
        for (int h = 0; h < 64; h++) {
            float  b  = svw[h];
            float2 uh = *(const float2*)(sUh + h * UPITCH + 2 * lane);
            accc.x += b * uh.x; accc.y += b * uh.y;
        }
        float2 cv = make_float2(tanhf(ah.x + accc.x), tanhf(ah.y + accc.y));
        float2 hv;
        hv.x = z.x * ht.x + (1.f - z.x) * cv.x;
        hv.y = z.y * ht.y + (1.f - z.y) * cv.y;
        ((float2*)(g_h + (size_t)(NL + p) * H))[lane] = hv;

        __threadfence();   // release
        __syncwarp();
        if (lane == 0) *(volatile int*)&g_flag[p] = 1;
    }
}

// ---------------- kernel 5: per-column max over parents (partial) ----------------
__global__ void k_rmax() {
    __shared__ float sred[4][64];
    int tid = threadIdx.x;               // 256
    int h2 = tid & 63, g = tid >> 6;
    int p0 = blockIdx.x * 128;
    float m = -1e30f;
    for (int r = g; r < 128; r += 4)
        m = fmaxf(m, g_h[(size_t)(NL + p0 + r) * H + h2]);
    sred[g][h2] = m;
    __syncthreads();
    if (tid < 64) {
        float mm = fmaxf(fmaxf(sred[0][tid], sred[1][tid]),
                         fmaxf(sred[2][tid], sred[3][tid]));
        g_partial[blockIdx.x * 64 + tid] = mm;
    }
}

// ---------------- kernel 6: final max + logits + softmax ----------------
__global__ void k_final(const float* __restrict__ Wout, const float* __restrict__ bout,
                        float* __restrict__ out) {
    __shared__ float fm[64];
    __shared__ float lg[4];
    int tid = threadIdx.x;               // 64
    float m = -1e30f;
    for (int b = 0; b < 64; b++) m = fmaxf(m, g_partial[b * 64 + tid]);
    fm[tid] = m;
    __syncthreads();
    if (tid < NCLASS) {
        float s = bout[tid];
        for (int h = 0; h < 64; h++) s += Wout[tid * 64 + h] * fm[h];
        lg[tid] = s;
    }
    __syncthreads();
    if (tid == 0) {
        float mx = fmaxf(fmaxf(lg[0], lg[1]), fmaxf(lg[2], lg[3]));
        float e0 = __expf(lg[0] - mx), e1 = __expf(lg[1] - mx);
        float e2 = __expf(lg[2] - mx), e3 = __expf(lg[3] - mx);
        float s = e0 + e1 + e2 + e3;
        out[0] = e0 / s; out[1] = e1 / s; out[2] = e2 / s; out[3] = e3 / s;
    }
}

// ---------------- launch ----------------
extern "C" void kernel_launch(void* const* d_in, const int* in_sizes, int n_in,
                              void* d_out, int out_size) {
    const float* x_word  = (const float*)d_in[0];
    const int*   x_index = (const int*)  d_in[1];
    const int*   tree    = (const int*)  d_in[2];
    const float* E       = (const float*)d_in[3];
    const float* Wz      = (const float*)d_in[4];
    const float* Uz      = (const float*)d_in[5];
    const float* bz      = (const float*)d_in[6];
    const float* Wr      = (const float*)d_in[7];
    const float* Ur      = (const float*)d_in[8];
    const float* br      = (const float*)d_in[9];
    const float* Wh      = (const float*)d_in[10];
    const float* Uh      = (const float*)d_in[11];
    const float* bh      = (const float*)d_in[12];
    const float* Wa      = (const float*)d_in[13];
    const float* Wout    = (const float*)d_in[14];
    const float* bout    = (const float*)d_in[15];
    float* out = (float*)d_out;

    const int smemLeaf = (2 * 64 * WPITCH + 2 * 64 + 16 * 64) * 4;  // 37888 B
    const int smemPar  = (3 * 64 * UPITCH + 8 * 64) * 4;            // 52736 B
    cudaFuncSetAttribute(k_leaf,    cudaFuncAttributeMaxDynamicSharedMemorySize, smemLeaf);
    cudaFuncSetAttribute(k_parents, cudaFuncAttributeMaxDynamicSharedMemorySize, smemPar);

    int dev = 0;
    cudaGetDevice(&dev);
    int sms = 0;
    if (cudaDeviceGetAttribute(&sms, cudaDevAttrMultiProcessorCount, dev) != cudaSuccess || sms <= 0)
        sms = 148;
    int nb = 0;
    if (cudaOccupancyMaxActiveBlocksPerMultiprocessor(&nb, k_parents, 256, smemPar) != cudaSuccess || nb < 1)
        nb = 1;
    int pgrid = sms * nb;                  // guaranteed co-resident
    if (pgrid > NP / 8) pgrid = NP / 8;
    if (pgrid < 1) pgrid = 1;

    k_prep<<<36, 256>>>(Wz, Wr, Wh, Wa);
    k_transpose<<<3125, 256>>>(E);
    k_embed<<<2048, 256>>>(x_word, x_index);
    k_leaf<<<512, 256, smemLeaf>>>(Wz, Wh, bz, bh);
    k_parents<<<pgrid, 256, smemPar>>>(Uz, Ur, Uh, tree, bz, br, bh);
    k_rmax<<<64, 256>>>();
    k_final<<<1, 64>>>(Wout, bout, out);
}